// round 13
// baseline (speedup 1.0000x reference)
#include <cuda_runtime.h>
#include <cstdint>
#include <cstddef>

#define Bsz 256
#define Tt  512
#define DIN 32
#define Hh  128
#define LATD 64
#define Gg  512   // 4*H

// Scratch (static __device__ — no allocations allowed)
__device__ float g_xg [(size_t)Bsz * Tt * Gg];   // permuted gate layout (see pos())
__device__ float g_hs2[(size_t)Bsz * Tt * Hh];   // decoder hidden states

typedef unsigned long long u64;

__device__ __forceinline__ void fma2(u64& d, u64 a, u64 b) {
    asm("fma.rn.f32x2 %0, %1, %2, %0;" : "+l"(d) : "l"(a), "l"(b));
}
__device__ __forceinline__ float lo2(u64 v) { return __uint_as_float((unsigned)(v & 0xffffffffu)); }
__device__ __forceinline__ float hi2(u64 v) { return __uint_as_float((unsigned)(v >> 32)); }

__device__ __forceinline__ float sigm(float x)   { return __fdividef(1.f, 1.f + __expf(-x)); }
__device__ __forceinline__ float tanh_f(float x) { return __fdividef(2.f, 1.f + __expf(-2.f * x)) - 1.f; }

// lstm thread j (e=j>>1, p=j&1) owns gate rows r0=e+128p and r1=256+e+128p.
// xg position: pos j holds gate row r0(j), pos 256+j holds r1(j).
__device__ __forceinline__ int xg_pos(int r) {
    return ((r >> 8) << 8) + ((r & 127) << 1) + ((r >> 7) & 1);
}

// ---------------------------------------------------------------------------
// Kernel A: g_xg[b,t,pos(j)] = sum_d x[b,t,d]*Wih[j,d] + bih[j] + bhh[j]
// ---------------------------------------------------------------------------
__global__ __launch_bounds__(512) void xg_kernel(
    const float* __restrict__ x, const float* __restrict__ Wih,
    const float* __restrict__ bih, const float* __restrict__ bhh)
{
    const int j = threadIdx.x;
    const int pos = xg_pos(j);
    const size_t row0 = (size_t)blockIdx.x * 128;
    __shared__ float xs[128 * DIN];   // 16 KB

    const float4* src = (const float4*)(x + row0 * DIN);
    float4* dst = (float4*)xs;
    for (int i = j; i < 128 * DIN / 4; i += 512) dst[i] = src[i];

    u64 w[16];
    const u64* wr = (const u64*)(Wih + j * DIN);
    #pragma unroll
    for (int p = 0; p < 16; p++) w[p] = wr[p];
    float bias = __ldg(bih + j) + __ldg(bhh + j);
    __syncthreads();

    for (int r = 0; r < 128; r++) {
        u64 acc = 0;
        const u64* xp = (const u64*)(xs + r * DIN);
        #pragma unroll
        for (int p = 0; p < 16; p++) fma2(acc, w[p], xp[p]);
        g_xg[(row0 + r) * Gg + pos] = lo2(acc) + hi2(acc) + bias;
    }
}

// ---------------------------------------------------------------------------
// Recurrent LSTM kernel, batch-phase pipelined. 128 CTAs x 256 threads,
// 2 independent batch rows (A=b0 on even lanes' state, B=b0+1 on odd).
// Thread j=(e,p): gate rows r0=e+128p (i/f), r1=256+e+128p (g/o);
// k=[0,96) in 192 regs, k=[96,128) in smem (shared across phases).
// Each step: [fmaA(t) || tailB(t-1)] BAR [fmaB(t) || tailA(t)] BAR.
// Tails (activation, shfl-combine, c/h update, STS) hide under the other
// batch's 128-fma2 block; xg loads prefetched one phase ahead.
// ---------------------------------------------------------------------------
#define W0_OFF   0
#define W1_OFF   32768
#define HA0_OFF  65536
#define HA1_OFF  66048
#define HB0_OFF  66560
#define HB1_OFF  67072
#define XB_OFF   67584
#define SMEM_BYTES 68096

template<bool DEC>
__global__ __launch_bounds__(256, 1) void lstm_kernel(
    const float* __restrict__ Whh,      // [512,128]
    const float* __restrict__ Wih,      // DEC: [512,64]
    const float* __restrict__ bih, const float* __restrict__ bhh,  // DEC only
    const float* __restrict__ enc_in,   // DEC: encoded [B,64]
    const float* __restrict__ Wl,  const float* __restrict__ bl,   // ENC
    float* __restrict__ out)            // ENC: encoded out [B,64]
{
    extern __shared__ char smem[];
    ulonglong2* Wsm0 = (ulonglong2*)(smem + W0_OFF);   // [8][256] row r0, k=96..127
    ulonglong2* Wsm1 = (ulonglong2*)(smem + W1_OFF);   // [8][256] row r1
    float* hAbuf[2] = { (float*)(smem + HA0_OFF), (float*)(smem + HA1_OFF) };
    float* hBbuf[2] = { (float*)(smem + HB0_OFF), (float*)(smem + HB1_OFF) };
    float* xb = (float*)(smem + XB_OFF);               // DEC: [2][64]

    const int j  = threadIdx.x;
    const int e  = j >> 1;
    const int p_ = j & 1;
    const int b0 = blockIdx.x * 2;
    const int r0 = e + 128 * p_;
    const int r1 = 256 + r0;

    // xg: DEC constants / ENC pointers
    float xg00 = 0.f, xg01 = 0.f, xg10 = 0.f, xg11 = 0.f;  // (row, batch)
    const float* pxA = nullptr; const float* pxB = nullptr;
    if (DEC) {
        if (j < 128) xb[j] = enc_in[b0 * LATD + j];
        __syncthreads();
        const float* wi0 = Wih + r0 * LATD;
        const float* wi1 = Wih + r1 * LATD;
        #pragma unroll 8
        for (int d = 0; d < LATD; d++) {
            float w0v = __ldg(wi0 + d), w1v = __ldg(wi1 + d);
            float x0 = xb[d], x1 = xb[64 + d];
            xg00 += w0v * x0; xg01 += w0v * x1;
            xg10 += w1v * x0; xg11 += w1v * x1;
        }
        float bb0 = __ldg(bih + r0) + __ldg(bhh + r0);
        float bb1 = __ldg(bih + r1) + __ldg(bhh + r1);
        xg00 += bb0; xg01 += bb0;
        xg10 += bb1; xg11 += bb1;
    } else {
        pxA = g_xg + (size_t)b0 * Tt * Gg + j;
        pxB = pxA + (size_t)Tt * Gg;
    }

    // Weights: k=[0,96) -> registers, k=[96,128) -> smem
    const float* wrow0 = Whh + r0 * Hh;
    const float* wrow1 = Whh + r1 * Hh;
    u64 w0[48], w1[48];
    #pragma unroll
    for (int q = 0; q < 48; q++) w0[q] = *(const u64*)(wrow0 + 2 * q);
    #pragma unroll
    for (int q = 0; q < 48; q++) w1[q] = *(const u64*)(wrow1 + 2 * q);
    #pragma unroll
    for (int q = 0; q < 8; q++) Wsm0[q * 256 + j] = *(const ulonglong2*)(wrow0 + 96 + 4 * q);
    #pragma unroll
    for (int q = 0; q < 8; q++) Wsm1[q * 256 + j] = *(const ulonglong2*)(wrow1 + 96 + 4 * q);
    if (j < 128) { hAbuf[0][j] = 0.f; hBbuf[0][j] = 0.f; }
    __syncthreads();

    float c = 0.f;                       // even lanes: c(e) of batch A; odd: batch B
    const float sc  = 2.f - (float)p_;   // gate1: tanh (p=0) / sigm (p=1)
    const float off = 1.f - (float)p_;
    float* hs2base = DEC ? (g_hs2 + ((size_t)(b0 + p_) * Tt) * Hh + e) : (float*)nullptr;

    // 128-fma2 block for one batch
    auto fma_block = [&](const float* hbuf, u64& a0, u64& a1) {
        const ulonglong2* hp = (const ulonglong2*)hbuf;
        #pragma unroll
        for (int q = 0; q < 24; q++) {
            ulonglong2 h4 = hp[q];
            fma2(a0, w0[2 * q], h4.x); fma2(a0, w0[2 * q + 1], h4.y);
            fma2(a1, w1[2 * q], h4.x); fma2(a1, w1[2 * q + 1], h4.y);
        }
        #pragma unroll
        for (int q = 0; q < 8; q++) {
            ulonglong2 h4 = hp[24 + q];
            ulonglong2 wa = Wsm0[q * 256 + j];
            ulonglong2 wb = Wsm1[q * 256 + j];
            fma2(a0, wa.x, h4.x); fma2(a0, wa.y, h4.y);
            fma2(a1, wb.x, h4.x); fma2(a1, wb.y, h4.y);
        }
    };

    // tail for batch sel (0=A on even lanes, 1=B on odd lanes)
    auto tail = [&](u64 s0, u64 s1, float g0, float g1,
                    float* hw, float* hs2p, int sel) {
        float v0 = sigm(lo2(s0) + hi2(s0) + g0);                    // i (p=0) / f (p=1)
        float v1 = sigm((lo2(s1) + hi2(s1) + g1) * sc) * sc - off;  // g (p=0) / o (p=1)
        float x0 = __shfl_xor_sync(0xffffffffu, v0, 1);
        float x1 = __shfl_xor_sync(0xffffffffu, v1, 1);
        if (p_ == sel) {
            float iv = p_ ? x0 : v0;
            float fv = p_ ? v0 : x0;
            float gv = p_ ? x1 : v1;
            float ov = p_ ? v1 : x1;
            c = fv * c + iv * gv;
            float h = ov * tanh_f(c);
            hw[e] = h;
            if (DEC) *hs2p = h;
        }
    };

    u64 aA0 = 0, aA1 = 0, aB0 = 0, aB1 = 0;
    float gA0 = xg00, gA1 = xg10, gB0 = xg01, gB1 = xg11;
    float pA0 = 0.f, pA1 = 0.f, pB0 = 0.f, pB1 = 0.f;
    if (!DEC) { pA0 = __ldg(pxA); pA1 = __ldg(pxA + 256); }

    for (int t = 0; t < Tt; t++) {
        // ---- phase A: gates(batch A, t) || tail(batch B, t-1) ----
        if (!DEC) {
            gA0 = pA0; gA1 = pA1;
            const float* qB = pxB + (size_t)t * Gg;          // prefetch for phase B
            pB0 = __ldg(qB); pB1 = __ldg(qB + 256);
        }
        aA0 = 0; aA1 = 0;
        fma_block(hAbuf[t & 1], aA0, aA1);
        if (t)
            tail(aB0, aB1, gB0, gB1, hBbuf[t & 1],
                 DEC ? hs2base + (size_t)(t - 1) * Hh : nullptr, 1);
        __syncthreads();

        // ---- phase B: gates(batch B, t) || tail(batch A, t) ----
        if (!DEC) {
            gB0 = pB0; gB1 = pB1;
            if (t + 1 < Tt) {                                // prefetch for next phase A
                const float* qA = pxA + (size_t)(t + 1) * Gg;
                pA0 = __ldg(qA); pA1 = __ldg(qA + 256);
            }
        }
        aB0 = 0; aB1 = 0;
        fma_block(hBbuf[t & 1], aB0, aB1);
        tail(aA0, aA1, gA0, gA1, hAbuf[(t + 1) & 1],
             DEC ? hs2base + (size_t)t * Hh : nullptr, 0);
        __syncthreads();
    }
    // drain: tail(batch B, 511) -> hBbuf[0]
    tail(aB0, aB1, gB0, gB1, hBbuf[0],
         DEC ? hs2base + (size_t)(Tt - 1) * Hh : nullptr, 1);
    __syncthreads();

    if (!DEC) {
        // h_last: batch A in hAbuf[0], batch B in hBbuf[0] (contiguous layouts)
        if (j < 128) {
            int rr = j >> 6, l = j & 63;
            const float* hsrc = rr ? hBbuf[0] : hAbuf[0];
            const float* wlr = Wl + l * Hh;
            float acc = __ldg(bl + l);
            #pragma unroll 16
            for (int k = 0; k < Hh; k++) acc += __ldg(wlr + k) * hsrc[k];
            out[(b0 + rr) * LATD + l] = acc;
        }
    }
}

// ---------------------------------------------------------------------------
// Kernel D: decoded[b,t,d] = sum_h g_hs2[b,t,h]*dec_Wl[d,h] + dec_bl[d]
// grid 2048 x 256. W transposed to [kpair][d] u64 layout (conflict-free);
// h read as u64 broadcast; packed-f32x2 MACs.
// ---------------------------------------------------------------------------
__global__ __launch_bounds__(256) void out_kernel(
    const float* __restrict__ Wl, const float* __restrict__ bl,
    float* __restrict__ out)
{
    __shared__ __align__(16) float hrow[64 * 128];   // 32 KB
    __shared__ __align__(16) u64 wlT2[64 * 32];      // 16 KB : [kp][d] pairs
    const int t = threadIdx.x;
    const size_t row0 = (size_t)blockIdx.x * 64;

    {
        const float4* src = (const float4*)(g_hs2 + row0 * Hh);
        float4* dst = (float4*)hrow;
        #pragma unroll
        for (int i = t; i < 64 * 128 / 4; i += 256) dst[i] = src[i];
        float* wf = (float*)wlT2;
        for (int i = t; i < 32 * 128; i += 256) {
            int d = i >> 7, k = i & 127;
            wf[(k >> 1) * 64 + d * 2 + (k & 1)] = Wl[i];
        }
    }
    __syncthreads();

    const int d  = t & 31;
    const int rb = t >> 5;   // warp-uniform -> hrow reads broadcast
    u64 acc[8];
    #pragma unroll
    for (int q = 0; q < 8; q++) acc[q] = 0;

    const u64* wp = wlT2 + d;
    const u64* h2 = (const u64*)hrow;
    #pragma unroll 8
    for (int kp = 0; kp < 64; kp++) {
        u64 w = wp[(size_t)kp * 32];
        #pragma unroll
        for (int q = 0; q < 8; q++)
            fma2(acc[q], w, h2[(rb + q * 8) * 64 + kp]);
    }
    float bias = __ldg(bl + d);
    #pragma unroll
    for (int q = 0; q < 8; q++)
        out[(row0 + rb + q * 8) * DIN + d] = lo2(acc[q]) + hi2(acc[q]) + bias;
}

// ---------------------------------------------------------------------------
extern "C" void kernel_launch(void* const* d_in, const int* in_sizes, int n_in,
                              void* d_out, int out_size)
{
    const float* x        = (const float*)d_in[0];
    const float* enc_Wih  = (const float*)d_in[1];
    const float* enc_Whh  = (const float*)d_in[2];
    const float* enc_bih  = (const float*)d_in[3];
    const float* enc_bhh  = (const float*)d_in[4];
    const float* enc_Wl   = (const float*)d_in[5];
    const float* enc_bl   = (const float*)d_in[6];
    const float* dec_Wih  = (const float*)d_in[7];
    const float* dec_Whh  = (const float*)d_in[8];
    const float* dec_bih  = (const float*)d_in[9];
    const float* dec_bhh  = (const float*)d_in[10];
    const float* dec_Wl   = (const float*)d_in[11];
    const float* dec_bl   = (const float*)d_in[12];
    float* out = (float*)d_out;

    cudaFuncSetAttribute((const void*)lstm_kernel<false>,
                         cudaFuncAttributeMaxDynamicSharedMemorySize, SMEM_BYTES);
    cudaFuncSetAttribute((const void*)lstm_kernel<true>,
                         cudaFuncAttributeMaxDynamicSharedMemorySize, SMEM_BYTES);

    // 1) input transform for encoder (permuted gate layout)
    xg_kernel<<<(Bsz * Tt) / 128, 512>>>(x, enc_Wih, enc_bih, enc_bhh);
    // 2) encoder recurrence + encoded projection (writes out[0 : 256*64))
    lstm_kernel<false><<<Bsz / 2, 256, SMEM_BYTES>>>(
        enc_Whh, nullptr, nullptr, nullptr, nullptr, enc_Wl, enc_bl, out);
    // 3) decoder recurrence (reads encoded from out, writes g_hs2)
    lstm_kernel<true><<<Bsz / 2, 256, SMEM_BYTES>>>(
        dec_Whh, dec_Wih, dec_bih, dec_bhh, out, nullptr, nullptr, nullptr);
    // 4) decoded projection (writes out[256*64 : end))
    out_kernel<<<(Bsz * Tt) / 64, 256>>>(dec_Wl, dec_bl, out + Bsz * LATD);
}

// round 16
// speedup vs baseline: 1.6594x; 1.6594x over previous
#include <cuda_runtime.h>
#include <cstdint>
#include <cstddef>

#define Bsz 256
#define Tt  512
#define DIN 32
#define Hh  128
#define LATD 64
#define Gg  512   // 4*H

// Scratch (static __device__ — no allocations allowed)
__device__ float g_xg [(size_t)Bsz * Tt * Gg];   // 256 MB: x @ Wih^T + bih + bhh
__device__ float g_hs2[(size_t)Bsz * Tt * Hh];   // 64 MB : decoder hidden states

typedef unsigned long long u64;

__device__ __forceinline__ void fma2(u64& d, u64 a, u64 b) {
    asm("fma.rn.f32x2 %0, %1, %2, %0;" : "+l"(d) : "l"(a), "l"(b));
}
__device__ __forceinline__ float lo2(u64 v) { return __uint_as_float((unsigned)(v & 0xffffffffu)); }
__device__ __forceinline__ float hi2(u64 v) { return __uint_as_float((unsigned)(v >> 32)); }

__device__ __forceinline__ float sigm(float x)   { return __fdividef(1.f, 1.f + __expf(-x)); }
__device__ __forceinline__ float tanh_f(float x) { return __fdividef(2.f, 1.f + __expf(-2.f * x)) - 1.f; }

// ---------------------------------------------------------------------------
// Kernel A: g_xg[b,t,j] = sum_d x[b,t,d]*Wih[j,d] + bih[j] + bhh[j]
// ---------------------------------------------------------------------------
__global__ __launch_bounds__(512) void xg_kernel(
    const float* __restrict__ x, const float* __restrict__ Wih,
    const float* __restrict__ bih, const float* __restrict__ bhh)
{
    const int j = threadIdx.x;
    const size_t row0 = (size_t)blockIdx.x * 128;
    __shared__ float xs[128 * DIN];   // 16 KB

    const float4* src = (const float4*)(x + row0 * DIN);
    float4* dst = (float4*)xs;
    for (int i = j; i < 128 * DIN / 4; i += 512) dst[i] = src[i];

    u64 w[16];
    const u64* wr = (const u64*)(Wih + j * DIN);
    #pragma unroll
    for (int p = 0; p < 16; p++) w[p] = wr[p];
    float bias = __ldg(bih + j) + __ldg(bhh + j);
    __syncthreads();

    for (int r = 0; r < 128; r++) {
        u64 acc = 0;
        const u64* xp = (const u64*)(xs + r * DIN);
        #pragma unroll
        for (int p = 0; p < 16; p++) fma2(acc, w[p], xp[p]);
        g_xg[(row0 + r) * Gg + j] = lo2(acc) + hi2(acc) + bias;
    }
}

// ---------------------------------------------------------------------------
// Recurrent LSTM kernel (R4 structure — measured best). 128 CTAs x 256
// threads, 2 batch rows per CTA. Thread j owns gate rows j and j+256.
// For each row, k=[0,96) lives in registers (192 regs), k=[96,128) in smem.
// h is kept in smem interleaved as hb[p] = (h0[2p],h0[2p+1],h1[2p],h1[2p+1])
// so one LDS.128 broadcast feeds both batch rows' packed-f32x2 FMAs.
// ---------------------------------------------------------------------------
#define WSMA_OFF 0
#define WSMB_OFF 32768
#define HB_OFF   65536
#define GB_OFF   66560
#define XB_OFF   70656
#define SMEM_BYTES 71680

template<bool DEC>
__global__ __launch_bounds__(256, 1) void lstm_kernel(
    const float* __restrict__ Whh,      // [512,128]
    const float* __restrict__ Wih,      // DEC: [512,64]
    const float* __restrict__ bih, const float* __restrict__ bhh,  // DEC only
    const float* __restrict__ enc_in,   // DEC: encoded [B,64]
    const float* __restrict__ Wl,  const float* __restrict__ bl,   // ENC
    float* __restrict__ out)            // ENC: encoded out [B,64]
{
    extern __shared__ char smem[];
    ulonglong2* WsmA = (ulonglong2*)(smem + WSMA_OFF);  // [8][256] : row j,   k=96..127
    ulonglong2* WsmB = (ulonglong2*)(smem + WSMB_OFF);  // [8][256] : row j+256
    float4*     hb   = (float4*)(smem + HB_OFF);        // [64] interleaved h (2 rows x 128)
    float*      gb   = (float*)(smem + GB_OFF);         // [2][4][128] gate values
    float*      xb   = (float*)(smem + XB_OFF);         // DEC: [2][64] encoded

    const int j  = threadIdx.x;
    const int b0 = blockIdx.x * 2;

    float xgA0 = 0.f, xgA1 = 0.f, xgB0 = 0.f, xgB1 = 0.f;  // DEC: t-invariant
    float nA0 = 0.f, nA1 = 0.f, nB0 = 0.f, nB1 = 0.f;      // ENC: prefetch regs
    const float* px = nullptr;

    if (DEC) {
        if (j < 128) xb[j] = enc_in[b0 * LATD + j];
        __syncthreads();
        float s00 = 0.f, s01 = 0.f, s10 = 0.f, s11 = 0.f;
        const float* wiA = Wih + j * LATD;
        const float* wiB = Wih + (j + 256) * LATD;
        #pragma unroll 8
        for (int d = 0; d < LATD; d++) {
            float wa = __ldg(wiA + d), wb = __ldg(wiB + d);
            float x0 = xb[d], x1 = xb[64 + d];
            s00 += wa * x0; s01 += wb * x0;
            s10 += wa * x1; s11 += wb * x1;
        }
        float bA = __ldg(bih + j) + __ldg(bhh + j);
        float bB = __ldg(bih + j + 256) + __ldg(bhh + j + 256);
        xgA0 = s00 + bA; xgA1 = s10 + bA;   // row j    : batch 0, batch 1
        xgB0 = s01 + bB; xgB1 = s11 + bB;   // row j+256: batch 0, batch 1
    } else {
        px = g_xg + (size_t)b0 * Tt * Gg + j;
        nA0 = __ldg(px);
        nA1 = __ldg(px + (size_t)Tt * Gg);
        nB0 = __ldg(px + 256);
        nB1 = __ldg(px + (size_t)Tt * Gg + 256);
    }

    // Weights: k=[0,96) to registers, k=[96,128) to smem
    const float* wrowA = Whh + j * Hh;
    const float* wrowB = Whh + (j + 256) * Hh;
    u64 wrA[48], wrB[48];
    #pragma unroll
    for (int p = 0; p < 48; p++) wrA[p] = *(const u64*)(wrowA + 2 * p);
    #pragma unroll
    for (int p = 0; p < 48; p++) wrB[p] = *(const u64*)(wrowB + 2 * p);
    #pragma unroll
    for (int q = 0; q < 8; q++) WsmA[q * 256 + j] = *(const ulonglong2*)(wrowA + 96 + 4 * q);
    #pragma unroll
    for (int q = 0; q < 8; q++) WsmB[q * 256 + j] = *(const ulonglong2*)(wrowB + 96 + 4 * q);
    if (j < 64) hb[j] = make_float4(0.f, 0.f, 0.f, 0.f);
    __syncthreads();

    float c = 0.f;                 // cell state for (row r_, element hx)
    const int r_ = j >> 7;
    const int hx = j & 127;

    for (int t = 0; t < Tt; t++) {
        float g_A0, g_A1, g_B0, g_B1;
        if (DEC) { g_A0 = xgA0; g_A1 = xgA1; g_B0 = xgB0; g_B1 = xgB1; }
        else {
            g_A0 = nA0; g_A1 = nA1; g_B0 = nB0; g_B1 = nB1;
            if (t + 1 < Tt) {
                const float* p2 = px + (size_t)(t + 1) * Gg;
                nA0 = __ldg(p2);
                nA1 = __ldg(p2 + (size_t)Tt * Gg);
                nB0 = __ldg(p2 + 256);
                nB1 = __ldg(p2 + (size_t)Tt * Gg + 256);
            }
        }
        u64 a0 = 0, a1 = 0, e0 = 0, e1 = 0;
        const ulonglong2* hp = (const ulonglong2*)hb;
        #pragma unroll
        for (int p = 0; p < 48; p++) {
            ulonglong2 h4 = hp[p];
            fma2(a0, wrA[p], h4.x); fma2(a1, wrA[p], h4.y);
            fma2(e0, wrB[p], h4.x); fma2(e1, wrB[p], h4.y);
        }
        #pragma unroll
        for (int q = 0; q < 8; q++) {
            ulonglong2 h4a = hp[48 + 2 * q];
            ulonglong2 h4b = hp[49 + 2 * q];
            ulonglong2 wa = WsmA[q * 256 + j];
            ulonglong2 wb = WsmB[q * 256 + j];
            fma2(a0, wa.x, h4a.x); fma2(a0, wa.y, h4b.x);
            fma2(a1, wa.x, h4a.y); fma2(a1, wa.y, h4b.y);
            fma2(e0, wb.x, h4a.x); fma2(e0, wb.y, h4b.x);
            fma2(e1, wb.x, h4a.y); fma2(e1, wb.y, h4b.y);
        }
        float vA0 = lo2(a0) + hi2(a0) + g_A0;   // gate row j    : i (j<128) / f
        float vA1 = lo2(a1) + hi2(a1) + g_A1;
        float vB0 = lo2(e0) + hi2(e0) + g_B0;   // gate row j+256: g (j<128) / o
        float vB1 = lo2(e1) + hi2(e1) + g_B1;
        vA0 = sigm(vA0); vA1 = sigm(vA1);
        if (j < 128) { vB0 = tanh_f(vB0); vB1 = tanh_f(vB1); }
        else         { vB0 = sigm(vB0);   vB1 = sigm(vB1);   }
        gb[j]             = vA0;  gb[512 + j]       = vA1;
        gb[256 + j]       = vB0;  gb[512 + 256 + j] = vB1;
        __syncthreads();

        // combine: thread j -> (row r_, h index hx)
        {
            const float* base = gb + r_ * 512;
            float iv = base[hx];
            float fv = base[128 + hx];
            float gv = base[256 + hx];
            float ov = base[384 + hx];
            c = fv * c + iv * gv;
            float h = ov * tanh_f(c);
            ((float*)hb)[(hx >> 1) * 4 + r_ * 2 + (hx & 1)] = h;
            if (DEC) g_hs2[((size_t)(b0 + r_) * Tt + t) * Hh + hx] = h;
        }
        __syncthreads();
    }

    if (!DEC) {
        // encoded = h_last @ enc_Wl^T + enc_bl  (64 outs x 2 rows)
        if (j < 128) {
            int rr = j >> 6, l = j & 63;
            const float* wlr = Wl + l * Hh;
            const float* hbf = (const float*)hb;
            float acc = __ldg(bl + l);
            #pragma unroll 16
            for (int k = 0; k < Hh; k++)
                acc += __ldg(wlr + k) * hbf[(k >> 1) * 4 + rr * 2 + (k & 1)];
            out[(b0 + rr) * LATD + l] = acc;
        }
    }
}

// ---------------------------------------------------------------------------
// Kernel D: decoded[b,t,d] = sum_h g_hs2[b,t,h]*dec_Wl[d,h] + dec_bl[d]
// grid 2048 x 256. Both streams 16B-vectorized: W stored [kp2][d] as
// ulonglong2 (k-quad per lane, 4 wf / 2kp, conflict-free) and h broadcast
// as ulonglong2 (1 wf per 16B). 6 wf/kp/warp vs 10 before.
// ---------------------------------------------------------------------------
__global__ __launch_bounds__(256) void out_kernel(
    const float* __restrict__ Wl, const float* __restrict__ bl,
    float* __restrict__ out)
{
    __shared__ __align__(16) float hrow[64 * 128];     // 32 KB
    __shared__ __align__(16) ulonglong2 wlT[32 * 32];  // 16 KB : [kp2][d] k-quads
    const int t = threadIdx.x;
    const size_t row0 = (size_t)blockIdx.x * 64;

    {
        const float4* src = (const float4*)(g_hs2 + row0 * Hh);
        float4* dst = (float4*)hrow;
        #pragma unroll
        for (int i = t; i < 64 * 128 / 4; i += 256) dst[i] = src[i];
        // transpose Wl [32 d][128 k] -> wlT[kp2][d] = k-quad (k=4*kp2..4*kp2+3)
        float* wf = (float*)wlT;
        for (int i = t; i < 32 * 128; i += 256) {
            int d = i >> 7, k = i & 127;
            wf[(k >> 2) * 128 + d * 4 + (k & 3)] = Wl[i];
        }
    }
    __syncthreads();

    const int d  = t & 31;
    const int rb = t >> 5;   // warp-uniform -> hrow reads broadcast
    u64 acc[8];
    #pragma unroll
    for (int q = 0; q < 8; q++) acc[q] = 0;

    const ulonglong2* h4 = (const ulonglong2*)hrow;    // [row][32] k-quads
    #pragma unroll 4
    for (int kp2 = 0; kp2 < 32; kp2++) {
        ulonglong2 w = wlT[kp2 * 32 + d];
        #pragma unroll
        for (int q = 0; q < 8; q++) {
            ulonglong2 h = h4[(rb + q * 8) * 32 + kp2];
            fma2(acc[q], w.x, h.x);
            fma2(acc[q], w.y, h.y);
        }
    }
    float bias = __ldg(bl + d);
    #pragma unroll
    for (int q = 0; q < 8; q++)
        out[(row0 + rb + q * 8) * DIN + d] = lo2(acc[q]) + hi2(acc[q]) + bias;
}

// ---------------------------------------------------------------------------
extern "C" void kernel_launch(void* const* d_in, const int* in_sizes, int n_in,
                              void* d_out, int out_size)
{
    const float* x        = (const float*)d_in[0];
    const float* enc_Wih  = (const float*)d_in[1];
    const float* enc_Whh  = (const float*)d_in[2];
    const float* enc_bih  = (const float*)d_in[3];
    const float* enc_bhh  = (const float*)d_in[4];
    const float* enc_Wl   = (const float*)d_in[5];
    const float* enc_bl   = (const float*)d_in[6];
    const float* dec_Wih  = (const float*)d_in[7];
    const float* dec_Whh  = (const float*)d_in[8];
    const float* dec_bih  = (const float*)d_in[9];
    const float* dec_bhh  = (const float*)d_in[10];
    const float* dec_Wl   = (const float*)d_in[11];
    const float* dec_bl   = (const float*)d_in[12];
    float* out = (float*)d_out;

    cudaFuncSetAttribute((const void*)lstm_kernel<false>,
                         cudaFuncAttributeMaxDynamicSharedMemorySize, SMEM_BYTES);
    cudaFuncSetAttribute((const void*)lstm_kernel<true>,
                         cudaFuncAttributeMaxDynamicSharedMemorySize, SMEM_BYTES);

    // 1) input transform for encoder
    xg_kernel<<<(Bsz * Tt) / 128, 512>>>(x, enc_Wih, enc_bih, enc_bhh);
    // 2) encoder recurrence + encoded projection (writes out[0 : 256*64))
    lstm_kernel<false><<<Bsz / 2, 256, SMEM_BYTES>>>(
        enc_Whh, nullptr, nullptr, nullptr, nullptr, enc_Wl, enc_bl, out);
    // 3) decoder recurrence (reads encoded from out, writes g_hs2)
    lstm_kernel<true><<<Bsz / 2, 256, SMEM_BYTES>>>(
        dec_Whh, dec_Wih, dec_bih, dec_bhh, out, nullptr, nullptr, nullptr);
    // 4) decoded projection (writes out[256*64 : end))
    out_kernel<<<(Bsz * Tt) / 64, 256>>>(dec_Wl, dec_bl, out + Bsz * LATD);
}